// round 15
// baseline (speedup 1.0000x reference)
#include <cuda_runtime.h>
#include <math.h>

#define DINLINE __device__ __forceinline__

constexpr int BB = 64;      // batch
constexpr int SS = 512;     // seq len
constexpr int HH = 1024;    // hidden
constexpr int GG = 4096;    // 4*H gates
constexpr int KDIM = 1024;  // contraction dim (IN == H == 1024)
constexpr int NBLK = 128;   // persistent recurrence blocks (1 wave, 1 block/SM)

// ---------------- scratch (device globals; no runtime allocation) ----------------
__device__ float g_pre [(size_t)SS * BB * GG];   // 512 MB, time-major [S][B][G]
__device__ float g_hseq[(size_t)BB * SS * HH];   // layer-0 output sequence [B][S][H]
__device__ float g_hbuf[2][BB * HH];             // double-buffered recurrent h
__device__ float g_c   [BB * HH];                // cell state (block-exclusive)
__device__ unsigned g_count;                     // grid-barrier arrival counter
__device__ volatile unsigned g_flag;             // grid-barrier phase flag

// ---------------- packed f32x2 helpers (sm_103a) ----------------
DINLINE unsigned long long pack_dup(float x) {
    unsigned long long r;
    asm("mov.b64 %0, {%1, %1};" : "=l"(r) : "f"(x));
    return r;
}
DINLINE void fma2(unsigned long long &acc, unsigned long long a, unsigned long long b) {
    asm("fma.rn.f32x2 %0, %1, %2, %0;" : "+l"(acc) : "l"(a), "l"(b));
}
DINLINE float2 unpack2(unsigned long long v) {
    float2 r;
    asm("mov.b64 {%0, %1}, %2;" : "=f"(r.x), "=f"(r.y) : "l"(v));
    return r;
}
DINLINE float sigmoidf_(float x) { return 1.0f / (1.0f + expf(-x)); }
DINLINE void team_bar(int id) {
    asm volatile("bar.sync %0, %1;" :: "r"(id), "r"(128) : "memory");
}

// Grid barrier: monotonic phase, equality spin. Safe: all NBLK blocks are
// co-resident (1 block/SM, 128 <= 148 SMs) and a spinning block cannot arrive
// at the next barrier, so the flag can never skip past a waiter's phase.
// Cross-launch/replay: stale flag value (513) never equals a live phase at
// the moment it is awaited (within a launch the flag passes 1..512 first).
DINLINE void grid_bar(unsigned phase) {
    __threadfence();                 // publish this thread's writes
    __syncthreads();
    if (threadIdx.x == 0) {
        if (atomicAdd(&g_count, 1u) == NBLK - 1u) {
            atomicExch(&g_count, 0u);
            __threadfence();
            g_flag = phase;
        } else {
            while (g_flag != phase) __nanosleep(64);
        }
    }
    __syncthreads();
    __threadfence();
}

// ---------------- batched input projection: g_pre = A @ W^T + bi + bh ----------------
// 128x128x16 tiles, 256 threads, 8x8 microtile, f32x2 FMA, ping-pong smem
// (one barrier per K-chunk), prefetch-before-compute, __stcs streaming output.
__global__ __launch_bounds__(256, 2) void gemm_pre_kernel(
    const float* __restrict__ Aext,
    const float* __restrict__ W,
    const float* __restrict__ bi,
    const float* __restrict__ bh,
    int use_hseq)
{
    constexpr int BK = 16;
    constexpr int NITER = KDIM / BK;            // 64
    __shared__ __align__(16) float As[2][BK][128];
    __shared__ __align__(16) float Bs[2][BK][128];

    const float* A = use_hseq ? g_hseq : Aext;
    int tid = threadIdx.x;
    int m0 = blockIdx.y * 128;
    int n0 = blockIdx.x * 128;

    int lr = tid >> 1;
    int lk = (tid & 1) * 8;
    const float* Ap = A + (size_t)(m0 + lr) * KDIM + lk;
    const float* Wp = W + (size_t)(n0 + lr) * KDIM + lk;

    int tx = tid & 15, ty = tid >> 4;

    unsigned long long acc[8][4];
    #pragma unroll
    for (int i = 0; i < 8; i++)
        #pragma unroll
        for (int j = 0; j < 4; j++) acc[i][j] = 0ull;

    float4 av0 = *(const float4*)(Ap + 0);
    float4 av1 = *(const float4*)(Ap + 4);
    float4 wv0 = *(const float4*)(Wp + 0);
    float4 wv1 = *(const float4*)(Wp + 4);

    for (int it = 0; it < NITER; ++it) {
        int buf = it & 1;
        As[buf][lk+0][lr]=av0.x; As[buf][lk+1][lr]=av0.y; As[buf][lk+2][lr]=av0.z; As[buf][lk+3][lr]=av0.w;
        As[buf][lk+4][lr]=av1.x; As[buf][lk+5][lr]=av1.y; As[buf][lk+6][lr]=av1.z; As[buf][lk+7][lr]=av1.w;
        Bs[buf][lk+0][lr]=wv0.x; Bs[buf][lk+1][lr]=wv0.y; Bs[buf][lk+2][lr]=wv0.z; Bs[buf][lk+3][lr]=wv0.w;
        Bs[buf][lk+4][lr]=wv1.x; Bs[buf][lk+5][lr]=wv1.y; Bs[buf][lk+6][lr]=wv1.z; Bs[buf][lk+7][lr]=wv1.w;
        __syncthreads();

        if (it + 1 < NITER) {
            int kk = (it + 1) * BK;
            av0 = *(const float4*)(Ap + kk);
            av1 = *(const float4*)(Ap + kk + 4);
            wv0 = *(const float4*)(Wp + kk);
            wv1 = *(const float4*)(Wp + kk + 4);
        }

        #pragma unroll
        for (int k = 0; k < BK; ++k) {
            float4 a0 = *(const float4*)&As[buf][k][ty*8];
            float4 a1 = *(const float4*)&As[buf][k][ty*8 + 4];
            ulonglong2 b01 = *(const ulonglong2*)&Bs[buf][k][tx*8];
            ulonglong2 b23 = *(const ulonglong2*)&Bs[buf][k][tx*8 + 4];
            float a[8] = {a0.x,a0.y,a0.z,a0.w,a1.x,a1.y,a1.z,a1.w};
            #pragma unroll
            for (int i = 0; i < 8; i++) {
                unsigned long long ad = pack_dup(a[i]);
                fma2(acc[i][0], ad, b01.x);
                fma2(acc[i][1], ad, b01.y);
                fma2(acc[i][2], ad, b23.x);
                fma2(acc[i][3], ad, b23.y);
            }
        }
    }

    int nbase = n0 + tx * 8;
    float bsum[8];
    #pragma unroll
    for (int j = 0; j < 8; j++) bsum[j] = bi[nbase + j] + bh[nbase + j];

    #pragma unroll
    for (int i = 0; i < 8; i++) {
        int m = m0 + ty * 8 + i;
        int b = m >> 9;                 // m / SS
        int s = m & (SS - 1);           // m % SS
        size_t crow = ((size_t)s * BB + b) * GG;
        #pragma unroll
        for (int jp = 0; jp < 4; jp++) {
            float2 v = unpack2(acc[i][jp]);
            v.x += bsum[jp*2 + 0];
            v.y += bsum[jp*2 + 1];
            __stcs((float2*)&g_pre[crow + nbase + jp*2], v);
        }
    }
}

// ---------------- persistent recurrence: ONE launch per layer ----------------
// Block ug owns units [ug*8, ug*8+8) -> 32 gate columns, all 64 batches.
// Wh slice (32 rows x 1024) cached ONCE in smem, transposed to [k][col].
// Per step: split-K (2 teams of 4 warps) with hs staging; same FMA microtile
// as before (8 fma2 per thread per k from 2 hs broadcasts + 1 wcache LDS.64).
// Steps separated by grid_bar (all 128 blocks co-resident). h double-buffered
// by parity; c block-exclusive. State re-zeroed at kernel start (replay-safe).
constexpr int KC = 64;
constexpr int KHALF = 512;
constexpr int SMEM_FLOATS = KDIM * 32 + 2 * KC * 64;   // wcache + hs = 40960
constexpr int SMEM_BYTES  = SMEM_FLOATS * 4;           // 163840 B

extern __shared__ float s_pool[];

__global__ __launch_bounds__(256, 1) void lstm_seq_kernel(
    const float* __restrict__ Wh,
    float* __restrict__ out_l1,
    float* __restrict__ hn,
    float* __restrict__ cn,
    int layer)
{
    float (*wc)[32]       = (float(*)[32])s_pool;                    // [1024][32]
    float (*hs)[KC][64]   = (float(*)[KC][64])(s_pool + KDIM * 32);  // [2][64][64]
    float (*gsm)[32][66]  = (float(*)[32][66])(s_pool + KDIM * 32);  // overlay on hs

    int tid  = threadIdx.x;
    int ug   = blockIdx.x;
    int kw   = tid >> 7;              // K-half team 0/1
    int t128 = tid & 127;
    int cp   = t128 & 15;             // col pair -> cols 2cp, 2cp+1
    int bg   = t128 >> 4;             // batch group 0..7
    int bar_id = kw + 1;

    // ---- cache Wh slice, transposed [k][col] (one-time) ----
    {
        int col = tid & 31;
        int kc8 = tid >> 5;           // 0..7, each covers 128 k
        int wrow = (col >> 3) * HH + ug * 8 + (col & 7);
        const float* src = Wh + (size_t)wrow * HH + kc8 * 128;
        #pragma unroll
        for (int i = 0; i < 32; i++) {
            float4 v = *(const float4*)(src + i * 4);
            int k = kc8 * 128 + i * 4;
            wc[k+0][col] = v.x; wc[k+1][col] = v.y;
            wc[k+2][col] = v.z; wc[k+3][col] = v.w;
        }
    }

    // ---- zero own h/c slice (deterministic per launch/replay) ----
    #pragma unroll
    for (int cc = 0; cc < 2; cc++) {
        int idx = tid + cc * 256;
        int b = idx >> 3, ul = idx & 7;
        int sidx = b * HH + ug * 8 + ul;
        g_hbuf[0][sidx] = 0.0f;
        g_c[sidx] = 0.0f;
    }
    grid_bar(1);                       // all zeroes + caches in place

    int hb_l = t128 & 63;              // batch row for h staging
    int hk_l = (t128 >> 6) << 5;       // 0 or 32

    unsigned phase = 2;
    for (int t = 0; t < SS; ++t, ++phase) {
        int rd = t & 1, wr = rd ^ 1;
        const float* hptr = g_hbuf[rd] + (size_t)hb_l * HH + kw * KHALF + hk_l;

        // hoisted pre-activation loads (retire under the FMA loop)
        const float* pre_t = g_pre + (size_t)t * BB * GG;
        float pre_c[2][4];
        #pragma unroll
        for (int cc = 0; cc < 2; cc++) {
            int idx = tid + cc * 256;
            int b = idx >> 3, ul = idx & 7;
            int unit = ug * 8 + ul;
            #pragma unroll
            for (int g = 0; g < 4; g++)
                pre_c[cc][g] = __ldcs(&pre_t[(size_t)b * GG + g * HH + unit]);
        }

        unsigned long long acc[2][4];
        #pragma unroll
        for (int c = 0; c < 2; c++)
            #pragma unroll
            for (int i = 0; i < 4; i++) acc[c][i] = 0ull;

        // prologue: h chunk 0
        float4 hv[8];
        #pragma unroll
        for (int j = 0; j < 8; j++) hv[j] = *(const float4*)(hptr + j*4);

        for (int kc = 0; kc < KHALF; kc += KC) {
            team_bar(bar_id);          // team's previous compute done with hs
            #pragma unroll
            for (int j = 0; j < 8; j++) {
                hs[kw][hk_l + j*4 + 0][hb_l] = hv[j].x;
                hs[kw][hk_l + j*4 + 1][hb_l] = hv[j].y;
                hs[kw][hk_l + j*4 + 2][hb_l] = hv[j].z;
                hs[kw][hk_l + j*4 + 3][hb_l] = hv[j].w;
            }
            team_bar(bar_id);

            if (kc + KC < KHALF) {
                #pragma unroll
                for (int j = 0; j < 8; j++) hv[j] = *(const float4*)(hptr + kc + KC + j*4);
            }

            #pragma unroll
            for (int k = 0; k < KC; ++k) {
                ulonglong2 a01 = *(const ulonglong2*)&hs[kw][k][bg*8];
                ulonglong2 a23 = *(const ulonglong2*)&hs[kw][k][bg*8 + 4];
                float2 wpair  = *(const float2*)&wc[kw*KHALF + kc + k][cp*2];
                unsigned long long w0 = pack_dup(wpair.x);
                unsigned long long w1 = pack_dup(wpair.y);
                fma2(acc[0][0], a01.x, w0); fma2(acc[0][1], a01.y, w0);
                fma2(acc[0][2], a23.x, w0); fma2(acc[0][3], a23.y, w0);
                fma2(acc[1][0], a01.x, w1); fma2(acc[1][1], a01.y, w1);
                fma2(acc[1][2], a23.x, w1); fma2(acc[1][3], a23.y, w1);
            }
        }

        // reduce split-K partials via gsm (overlays hs; cross-team -> full barriers)
        __syncthreads();
        #pragma unroll
        for (int c = 0; c < 2; c++)
            #pragma unroll
            for (int i = 0; i < 4; i++) {
                float2 v = unpack2(acc[c][i]);
                *(float2*)&gsm[kw][cp*2 + c][bg*8 + i*2] = v;
            }
        __syncthreads();

        // activation + state update: 512 cells, 2 per thread
        #pragma unroll
        for (int cc = 0; cc < 2; cc++) {
            int idx = tid + cc * 256;
            int b = idx >> 3, ul = idx & 7;
            float gates[4];
            #pragma unroll
            for (int g = 0; g < 4; g++)
                gates[g] = gsm[0][g*8 + ul][b] + gsm[1][g*8 + ul][b] + pre_c[cc][g];
            float iv = sigmoidf_(gates[0]);
            float fv = sigmoidf_(gates[1]);
            float gv = tanhf    (gates[2]);
            float ov = sigmoidf_(gates[3]);
            int unit = ug * 8 + ul;
            int sidx = b * HH + unit;
            float cprev = g_c[sidx];
            float cnew  = fv * cprev + iv * gv;
            g_c[sidx] = cnew;
            float hv_ = ov * tanhf(cnew);
            g_hbuf[wr][sidx] = hv_;
            size_t oidx = ((size_t)b * SS + t) * HH + unit;
            if (layer == 0) g_hseq[oidx] = hv_;
            else            __stcs(&out_l1[oidx], hv_);
            if (t == SS - 1) { __stcs(&hn[sidx], hv_); __stcs(&cn[sidx], cnew); }
        }

        grid_bar(phase);   // all blocks done with step t (reads AND writes)
    }
}

// ---------------- host driver: 4 graph nodes total ----------------
extern "C" void kernel_launch(void* const* d_in, const int* in_sizes, int n_in,
                              void* d_out, int out_size)
{
    (void)in_sizes; (void)n_in; (void)out_size;
    const float* x   = (const float*)d_in[0];
    const float* Wi0 = (const float*)d_in[1];
    const float* Wh0 = (const float*)d_in[2];
    const float* bi0 = (const float*)d_in[3];
    const float* bh0 = (const float*)d_in[4];
    const float* Wi1 = (const float*)d_in[5];
    const float* Wh1 = (const float*)d_in[6];
    const float* bi1 = (const float*)d_in[7];
    const float* bh1 = (const float*)d_in[8];

    float* out = (float*)d_out;                       // [B, S, H]
    float* hn  = out + (size_t)BB * SS * HH;          // [L, B, H]
    float* cn  = hn + 2 * BB * HH;                    // [L, B, H]

    // enable 160 KB dynamic smem for the persistent kernel (idempotent)
    cudaFuncSetAttribute(lstm_seq_kernel,
                         cudaFuncAttributeMaxDynamicSharedMemorySize, SMEM_BYTES);

    dim3 gemm_grid(GG / 128, (BB * SS) / 128);        // (32, 256)

    gemm_pre_kernel<<<gemm_grid, 256>>>(x, Wi0, bi0, bh0, /*use_hseq=*/0);
    lstm_seq_kernel<<<NBLK, 256, SMEM_BYTES>>>(Wh0, out, hn, cn, /*layer=*/0);

    gemm_pre_kernel<<<gemm_grid, 256>>>(nullptr, Wi1, bi1, bh1, /*use_hseq=*/1);
    lstm_seq_kernel<<<NBLK, 256, SMEM_BYTES>>>(Wh1, out, hn + BB * HH, cn + BB * HH, /*layer=*/1);
}

// round 16
// speedup vs baseline: 1.0928x; 1.0928x over previous
#include <cuda_runtime.h>
#include <math.h>

#define DINLINE __device__ __forceinline__

constexpr int BB = 64;      // batch
constexpr int SS = 512;     // seq len
constexpr int HH = 1024;    // hidden
constexpr int GG = 4096;    // 4*H gates
constexpr int KDIM = 1024;  // contraction dim (IN == H == 1024)
constexpr int NBLK = 128;   // persistent recurrence blocks (1 wave, 1 block/SM)

// ---------------- scratch (device globals; no runtime allocation) ----------------
__device__ float g_pre [(size_t)SS * BB * GG];   // 512 MB, time-major [S][B][G]
__device__ float g_hseq[(size_t)BB * SS * HH];   // layer-0 output sequence [B][S][H]
__device__ float g_hbuf[2][BB * HH];             // double-buffered recurrent h
__device__ float g_c   [BB * HH];                // cell state (block-exclusive)
__device__ unsigned g_count;                     // grid-barrier arrival counter
__device__ unsigned g_flag;                      // grid-barrier phase flag

// ---------------- packed f32x2 helpers (sm_103a) ----------------
DINLINE unsigned long long pack_dup(float x) {
    unsigned long long r;
    asm("mov.b64 %0, {%1, %1};" : "=l"(r) : "f"(x));
    return r;
}
DINLINE void fma2(unsigned long long &acc, unsigned long long a, unsigned long long b) {
    asm("fma.rn.f32x2 %0, %1, %2, %0;" : "+l"(acc) : "l"(a), "l"(b));
}
DINLINE float2 unpack2(unsigned long long v) {
    float2 r;
    asm("mov.b64 {%0, %1}, %2;" : "=f"(r.x), "=f"(r.y) : "l"(v));
    return r;
}
DINLINE float sigmoidf_(float x) { return 1.0f / (1.0f + expf(-x)); }

// Grid barrier, release/acquire version (no per-thread MEMBAR.GPU).
// Chain: writer's ST -> bar.sync (cta acq_rel) -> leader atom.add.release.gpu
// -> waiter ld.acquire.gpu -> bar.sync -> reader. Same chain grid_group::sync uses.
// All 128 blocks co-resident (1 block/SM via smem) -> no deadlock. Monotonic
// phases 1..513 per launch; count self-resets before the release of the flag.
DINLINE void grid_bar(unsigned phase) {
    __syncthreads();
    if (threadIdx.x == 0) {
        unsigned old;
        asm volatile("atom.add.release.gpu.u32 %0, [%1], %2;"
                     : "=r"(old) : "l"(&g_count), "r"(1u) : "memory");
        if (old == NBLK - 1u) {
            asm volatile("st.relaxed.gpu.u32 [%0], %1;" :: "l"(&g_count), "r"(0u) : "memory");
            asm volatile("st.release.gpu.u32 [%0], %1;" :: "l"(&g_flag), "r"(phase) : "memory");
        } else {
            unsigned v;
            for (;;) {
                asm volatile("ld.acquire.gpu.u32 %0, [%1];" : "=r"(v) : "l"(&g_flag) : "memory");
                if (v == phase) break;
                __nanosleep(32);
            }
        }
    }
    __syncthreads();
}

// ---------------- batched input projection: g_pre = A @ W^T + bi + bh ----------------
// Unchanged from R15 (measured at its L1=FMA knee): 128x128x16 tiles, 256 thr,
// 8x8 microtile, f32x2, ping-pong smem (1 barrier/chunk), __stcs streaming out.
__global__ __launch_bounds__(256, 2) void gemm_pre_kernel(
    const float* __restrict__ Aext,
    const float* __restrict__ W,
    const float* __restrict__ bi,
    const float* __restrict__ bh,
    int use_hseq)
{
    constexpr int BK = 16;
    constexpr int NITER = KDIM / BK;            // 64
    __shared__ __align__(16) float As[2][BK][128];
    __shared__ __align__(16) float Bs[2][BK][128];

    const float* A = use_hseq ? g_hseq : Aext;
    int tid = threadIdx.x;
    int m0 = blockIdx.y * 128;
    int n0 = blockIdx.x * 128;

    int lr = tid >> 1;
    int lk = (tid & 1) * 8;
    const float* Ap = A + (size_t)(m0 + lr) * KDIM + lk;
    const float* Wp = W + (size_t)(n0 + lr) * KDIM + lk;

    int tx = tid & 15, ty = tid >> 4;

    unsigned long long acc[8][4];
    #pragma unroll
    for (int i = 0; i < 8; i++)
        #pragma unroll
        for (int j = 0; j < 4; j++) acc[i][j] = 0ull;

    float4 av0 = *(const float4*)(Ap + 0);
    float4 av1 = *(const float4*)(Ap + 4);
    float4 wv0 = *(const float4*)(Wp + 0);
    float4 wv1 = *(const float4*)(Wp + 4);

    for (int it = 0; it < NITER; ++it) {
        int buf = it & 1;
        As[buf][lk+0][lr]=av0.x; As[buf][lk+1][lr]=av0.y; As[buf][lk+2][lr]=av0.z; As[buf][lk+3][lr]=av0.w;
        As[buf][lk+4][lr]=av1.x; As[buf][lk+5][lr]=av1.y; As[buf][lk+6][lr]=av1.z; As[buf][lk+7][lr]=av1.w;
        Bs[buf][lk+0][lr]=wv0.x; Bs[buf][lk+1][lr]=wv0.y; Bs[buf][lk+2][lr]=wv0.z; Bs[buf][lk+3][lr]=wv0.w;
        Bs[buf][lk+4][lr]=wv1.x; Bs[buf][lk+5][lr]=wv1.y; Bs[buf][lk+6][lr]=wv1.z; Bs[buf][lk+7][lr]=wv1.w;
        __syncthreads();

        if (it + 1 < NITER) {
            int kk = (it + 1) * BK;
            av0 = *(const float4*)(Ap + kk);
            av1 = *(const float4*)(Ap + kk + 4);
            wv0 = *(const float4*)(Wp + kk);
            wv1 = *(const float4*)(Wp + kk + 4);
        }

        #pragma unroll
        for (int k = 0; k < BK; ++k) {
            float4 a0 = *(const float4*)&As[buf][k][ty*8];
            float4 a1 = *(const float4*)&As[buf][k][ty*8 + 4];
            ulonglong2 b01 = *(const ulonglong2*)&Bs[buf][k][tx*8];
            ulonglong2 b23 = *(const ulonglong2*)&Bs[buf][k][tx*8 + 4];
            float a[8] = {a0.x,a0.y,a0.z,a0.w,a1.x,a1.y,a1.z,a1.w};
            #pragma unroll
            for (int i = 0; i < 8; i++) {
                unsigned long long ad = pack_dup(a[i]);
                fma2(acc[i][0], ad, b01.x);
                fma2(acc[i][1], ad, b01.y);
                fma2(acc[i][2], ad, b23.x);
                fma2(acc[i][3], ad, b23.y);
            }
        }
    }

    int nbase = n0 + tx * 8;
    float bsum[8];
    #pragma unroll
    for (int j = 0; j < 8; j++) bsum[j] = bi[nbase + j] + bh[nbase + j];

    #pragma unroll
    for (int i = 0; i < 8; i++) {
        int m = m0 + ty * 8 + i;
        int b = m >> 9;                 // m / SS
        int s = m & (SS - 1);           // m % SS
        size_t crow = ((size_t)s * BB + b) * GG;
        #pragma unroll
        for (int jp = 0; jp < 4; jp++) {
            float2 v = unpack2(acc[i][jp]);
            v.x += bsum[jp*2 + 0];
            v.y += bsum[jp*2 + 1];
            __stcs((float2*)&g_pre[crow + nbase + jp*2], v);
        }
    }
}

// ---------------- persistent recurrence: ONE launch per layer ----------------
// Block ug owns units [ug*8, ug*8+8) -> 32 gate cols, all 64 batches.
// NEW (measured L1-bound fix): 8 WARP-PRIVATE K-eighths. Warp w owns
// k in [w*128, w*128+128). Lane = (bq = lane>>2: batches bq*8..+8) x
// (cg = lane&3: cols cg*8..+8) -> 32 fma2 per lane per k from 4 LDS.128
// (vs 8 fma2 from 3 LDS before): compute L1 wavefronts/step drop 37K -> 16.4K
// (= the FMA floor). No intra-K barriers (warp-private staging, __syncwarp).
// 8-way split-K partials reduced via gsm overlay under full __syncthreads.
constexpr int KC = 32;                 // staging chunk (k per chunk)
constexpr int HSP = 68;                // hs row pad: 16B-aligned, STS conflict-free
constexpr int WC_FLOATS = KDIM * 32;                 // 32768
constexpr int HS_FLOATS = 8 * KC * HSP;              // 17408 (gsm 8*32*66=16896 fits)
constexpr int SMEM_BYTES = (WC_FLOATS + HS_FLOATS) * 4;   // 200704 B

extern __shared__ float s_pool[];

__global__ __launch_bounds__(256, 1) void lstm_seq_kernel(
    const float* __restrict__ Wh,
    float* __restrict__ out_l1,
    float* __restrict__ hn,
    float* __restrict__ cn,
    int layer)
{
    float* wcp = s_pool;                                        // [1024][32] Wh^T slice
    float (*hsall)[KC][HSP] = (float(*)[KC][HSP])(s_pool + WC_FLOATS); // [8][32][68]
    float (*gsm)[32][66]    = (float(*)[32][66])(s_pool + WC_FLOATS);  // overlay

    int tid  = threadIdx.x;
    int ug   = blockIdx.x;
    int w    = tid >> 5;              // warp id = K-eighth owner
    int lane = tid & 31;
    int bq   = lane >> 2;             // batch group: b in [bq*8, bq*8+8)
    int cg   = lane & 3;              // col group:   c in [cg*8, cg*8+8)

    // ---- cache Wh slice, transposed [k][col] (one-time) ----
    {
        int col = tid & 31;
        int kc8 = tid >> 5;           // 0..7, each covers 128 k
        int wrow = (col >> 3) * HH + ug * 8 + (col & 7);
        const float* src = Wh + (size_t)wrow * HH + kc8 * 128;
        #pragma unroll
        for (int i = 0; i < 32; i++) {
            float4 v = *(const float4*)(src + i * 4);
            int k = kc8 * 128 + i * 4;
            wcp[(k+0)*32 + col] = v.x; wcp[(k+1)*32 + col] = v.y;
            wcp[(k+2)*32 + col] = v.z; wcp[(k+3)*32 + col] = v.w;
        }
    }

    // ---- zero own h/c slice (deterministic per launch/replay) ----
    #pragma unroll
    for (int cc = 0; cc < 2; cc++) {
        int idx = tid + cc * 256;
        int b = idx >> 3, ul = idx & 7;
        int sidx = b * HH + ug * 8 + ul;
        g_hbuf[0][sidx] = 0.0f;
        g_c[sidx] = 0.0f;
    }
    grid_bar(1);                       // zeroes + wc cache in place, grid-wide

    unsigned phase = 2;
    for (int t = 0; t < SS; ++t, ++phase) {
        int rd = t & 1, wr = rd ^ 1;
        const float* hsrc = g_hbuf[rd];

        // hoisted pre-activation loads (retire under the FMA loop)
        const float* pre_t = g_pre + (size_t)t * BB * GG;
        float pre_c[2][4];
        #pragma unroll
        for (int cc = 0; cc < 2; cc++) {
            int idx = tid + cc * 256;
            int b = idx >> 3, ul = idx & 7;
            int unit = ug * 8 + ul;
            #pragma unroll
            for (int g = 0; g < 4; g++)
                pre_c[cc][g] = __ldcs(&pre_t[(size_t)b * GG + g * HH + unit]);
        }

        unsigned long long acc[8][4];
        #pragma unroll
        for (int c = 0; c < 8; c++)
            #pragma unroll
            for (int p = 0; p < 4; p++) acc[c][p] = 0ull;

        // ---- warp-private K-eighth: 4 chunks of KC=32 ----
        const float* h1 = hsrc + (size_t)lane * HH + w * 128;        // row `lane`
        const float* h2 = hsrc + (size_t)(lane + 32) * HH + w * 128; // row `lane+32`
        #pragma unroll 1
        for (int cb = 0; cb < 4; ++cb) {
            int kb = cb * KC;
            // stage h[0..64)[kb..kb+32) transposed into this warp's hs buffer.
            // STS banks: (k*HSP + b)%32 with b = lane distinct -> conflict-free.
            #pragma unroll
            for (int j = 0; j < 8; j++) {
                float4 v1 = *(const float4*)(h1 + kb + 4*j);
                float4 v2 = *(const float4*)(h2 + kb + 4*j);
                hsall[w][4*j+0][lane]    = v1.x; hsall[w][4*j+1][lane]    = v1.y;
                hsall[w][4*j+2][lane]    = v1.z; hsall[w][4*j+3][lane]    = v1.w;
                hsall[w][4*j+0][lane+32] = v2.x; hsall[w][4*j+1][lane+32] = v2.y;
                hsall[w][4*j+2][lane+32] = v2.z; hsall[w][4*j+3][lane+32] = v2.w;
            }
            __syncwarp();

            const float* wrow_base = wcp + (size_t)(w * 128 + kb) * 32 + cg * 8;
            #pragma unroll 8
            for (int kk = 0; kk < KC; ++kk) {
                ulonglong2 a01 = *(const ulonglong2*)&hsall[w][kk][bq*8];
                ulonglong2 a23 = *(const ulonglong2*)&hsall[w][kk][bq*8 + 4];
                float4 w0 = *(const float4*)(wrow_base + kk*32);
                float4 w1 = *(const float4*)(wrow_base + kk*32 + 4);
                float wv[8] = {w0.x,w0.y,w0.z,w0.w,w1.x,w1.y,w1.z,w1.w};
                #pragma unroll
                for (int c = 0; c < 8; c++) {
                    unsigned long long wd = pack_dup(wv[c]);
                    fma2(acc[c][0], a01.x, wd);
                    fma2(acc[c][1], a01.y, wd);
                    fma2(acc[c][2], a23.x, wd);
                    fma2(acc[c][3], a23.y, wd);
                }
            }
            __syncwarp();   // compute done before next chunk's staging overwrites hs
        }

        // ---- reduce 8 split-K partials via gsm (overlays hs; full barriers) ----
        __syncthreads();
        #pragma unroll
        for (int c = 0; c < 8; c++)
            #pragma unroll
            for (int p = 0; p < 4; p++) {
                float2 v = unpack2(acc[c][p]);
                *(float2*)&gsm[w][cg*8 + c][bq*8 + 2*p] = v;
            }
        __syncthreads();

        // ---- activation + state update: 512 cells, 2 per thread ----
        #pragma unroll
        for (int cc = 0; cc < 2; cc++) {
            int idx = tid + cc * 256;
            int b = idx >> 3, ul = idx & 7;
            float gates[4];
            #pragma unroll
            for (int g = 0; g < 4; g++) {
                float s = pre_c[cc][g];
                #pragma unroll
                for (int w2 = 0; w2 < 8; w2++) s += gsm[w2][g*8 + ul][b];
                gates[g] = s;
            }
            float iv = sigmoidf_(gates[0]);
            float fv = sigmoidf_(gates[1]);
            float gv = tanhf    (gates[2]);
            float ov = sigmoidf_(gates[3]);
            int unit = ug * 8 + ul;
            int sidx = b * HH + unit;
            float cprev = g_c[sidx];
            float cnew  = fv * cprev + iv * gv;
            g_c[sidx] = cnew;
            float hv_ = ov * tanhf(cnew);
            g_hbuf[wr][sidx] = hv_;
            size_t oidx = ((size_t)b * SS + t) * HH + unit;
            if (layer == 0) g_hseq[oidx] = hv_;
            else            __stcs(&out_l1[oidx], hv_);
            if (t == SS - 1) { __stcs(&hn[sidx], hv_); __stcs(&cn[sidx], cnew); }
        }

        grid_bar(phase);   // all blocks done with step t (reads AND writes)
    }
}

// ---------------- host driver: 4 graph nodes total ----------------
extern "C" void kernel_launch(void* const* d_in, const int* in_sizes, int n_in,
                              void* d_out, int out_size)
{
    (void)in_sizes; (void)n_in; (void)out_size;
    const float* x   = (const float*)d_in[0];
    const float* Wi0 = (const float*)d_in[1];
    const float* Wh0 = (const float*)d_in[2];
    const float* bi0 = (const float*)d_in[3];
    const float* bh0 = (const float*)d_in[4];
    const float* Wi1 = (const float*)d_in[5];
    const float* Wh1 = (const float*)d_in[6];
    const float* bi1 = (const float*)d_in[7];
    const float* bh1 = (const float*)d_in[8];

    float* out = (float*)d_out;                       // [B, S, H]
    float* hn  = out + (size_t)BB * SS * HH;          // [L, B, H]
    float* cn  = hn + 2 * BB * HH;                    // [L, B, H]

    cudaFuncSetAttribute(lstm_seq_kernel,
                         cudaFuncAttributeMaxDynamicSharedMemorySize, SMEM_BYTES);

    dim3 gemm_grid(GG / 128, (BB * SS) / 128);        // (32, 256)

    gemm_pre_kernel<<<gemm_grid, 256>>>(x, Wi0, bi0, bh0, /*use_hseq=*/0);
    lstm_seq_kernel<<<NBLK, 256, SMEM_BYTES>>>(Wh0, out, hn, cn, /*layer=*/0);

    gemm_pre_kernel<<<gemm_grid, 256>>>(nullptr, Wi1, bi1, bh1, /*use_hseq=*/1);
    lstm_seq_kernel<<<NBLK, 256, SMEM_BYTES>>>(Wh1, out, hn + BB * HH, cn + BB * HH, /*layer=*/1);
}